// round 6
// baseline (speedup 1.0000x reference)
#include <cuda_runtime.h>

// Inputs (metadata order): z [8192*128] f32 (UNUSED), risk [B] f32, time [B] f32, event [B] i32.
// Output: single f32 scalar = mean hinge over pairs (time[i] < time[j] && event[i]==1).
//
// Two-kernel plan:
//   K1: bucket-partition all rows by time into 64 buckets (approximate sort) into g_j;
//       simultaneously bucket the event==1 subset (with risk+1 prestored) into g_i.
//   K2: (i-chunk x j-chunk) grid over the bucketed arrays. Per block, classify by
//       exact chunk time ranges:  skip / predicate-free / mixed.  Free blocks run a
//       3-flop-per-pair loop with a closed-form count; only the thin time-diagonal
//       band pays the per-pair predicate.

#define B_CAP  8192
#define NB     64
#define TPB1   1024
#define EPT    8            // elements per thread in K1 (TPB1*EPT >= B_CAP)

#define TPB2   128
#define ICH    256          // compacted event i's per block (2 per thread)
#define JCH    256          // j's per block (2 per thread into smem)

__device__ float2             g_j[B_CAP];   // (risk, time), time-bucketed
__device__ float2             g_i[B_CAP];   // (risk+1, time), event==1 only, time-bucketed
__device__ int                g_ni;
__device__ double             g_total;      // zeroed at load; reset by last K2 block
__device__ unsigned long long g_cnt;
__device__ unsigned int       g_done;

// ---------------- K1: bucket partition ----------------
__global__ __launch_bounds__(TPB1) void k_bucket(const float* __restrict__ risk,
                                                 const float* __restrict__ time_,
                                                 const int*   __restrict__ event,
                                                 int n) {
    __shared__ int jc[NB];
    __shared__ int ic[NB];
    const int tid = threadIdx.x;

    if (tid < NB) { jc[tid] = 0; ic[tid] = 0; }
    __syncthreads();

    float tv[EPT], rv[EPT];
    int   bv[EPT];
    bool  ev[EPT], va[EPT];

    #pragma unroll
    for (int e = 0; e < EPT; e++) {
        int idx = tid + e * TPB1;
        bool valid = idx < n;
        va[e] = valid;
        float t = valid ? time_[idx] : 0.0f;
        rv[e]   = valid ? risk[idx]  : 0.0f;
        ev[e]   = valid && (event[idx] == 1);
        int b = (int)(t * (float)NB);
        b = b < 0 ? 0 : (b > NB - 1 ? NB - 1 : b);
        bv[e] = b;
        tv[e] = t;
        if (valid) atomicAdd(&jc[b], 1);
        if (ev[e]) atomicAdd(&ic[b], 1);
    }
    __syncthreads();

    if (tid == 0) {                       // exclusive prefix over 64 buckets
        int aj = 0, ai = 0;
        #pragma unroll
        for (int b = 0; b < NB; b++) {
            int cj = jc[b], ci = ic[b];
            jc[b] = aj; ic[b] = ai;
            aj += cj;  ai += ci;
        }
        g_ni = ai;
    }
    __syncthreads();

    #pragma unroll
    for (int e = 0; e < EPT; e++) {
        if (va[e]) {
            int d = atomicAdd(&jc[bv[e]], 1);
            g_j[d] = make_float2(rv[e], tv[e]);
            if (ev[e]) {
                int di = atomicAdd(&ic[bv[e]], 1);
                g_i[di] = make_float2(rv[e] + 1.0f, tv[e]);
            }
        }
    }
}

// ---------------- K2: classified pair loop ----------------
__global__ __launch_bounds__(TPB2) void k_pairs(float* __restrict__ out,
                                                int n, unsigned int nblocks) {
    __shared__ float sjr[JCH];            // risk_j
    __shared__ int   sjt[JCH];            // time_j bits (ints; time >= 0 or -inf pad)
    __shared__ float rmin[2][TPB2 / 32];  // cross-warp scratch: [0]=mins, [1]=maxs
    __shared__ float rmax[2][TPB2 / 32];
    __shared__ float swsum[TPB2 / 32];
    __shared__ int   swcnt[TPB2 / 32];

    const int   tid  = threadIdx.x;
    const int   lane = tid & 31;
    const int   w    = tid >> 5;
    const int   i0   = blockIdx.x * ICH;
    const int   j0   = blockIdx.y * JCH;
    const int   ni   = g_ni;
    const float PINF = __int_as_float(0x7f800000);
    const float NINF = __int_as_float(0xff800000);

    float s_acc = 0.0f;
    int   c_acc = 0;
    bool  free_blk = false;
    int   ni_blk = 0, nj_blk = 0;

    if (i0 < ni && j0 < n) {
        // ---- load j-chunk into shared; track min/max time ----
        float tminj = PINF, tmaxj = NINF;
        #pragma unroll
        for (int kk = 0; kk < 2; kk++) {
            int k = tid + kk * TPB2;
            int j = j0 + k;
            float rj = PINF;        // pad: contributes 0 in free loop
            int   tjb = 0xff800000; // -inf bits: predicate never true in mixed loop
            if (j < n) {
                float2 v = g_j[j];
                rj  = v.x;
                tjb = __float_as_int(v.y);
                tminj = fminf(tminj, v.y);
                tmaxj = fmaxf(tmaxj, v.y);
            }
            sjr[k] = rj;
            sjt[k] = tjb;
        }

        // ---- load 2 i's into registers; track min/max time ----
        float tmini = PINF, tmaxi = NINF;
        float r0 = NINF, r1 = NINF;          // pad: contributes 0 in free loop
        int   t0b = 0x7f800000, t1b = 0x7f800000;  // +inf bits: predicate never true
        int ia = i0 + tid, ib = i0 + tid + TPB2;
        if (ia < ni) {
            float2 u = g_i[ia];
            r0 = u.x; t0b = __float_as_int(u.y);
            tmini = fminf(tmini, u.y); tmaxi = fmaxf(tmaxi, u.y);
        }
        if (ib < ni) {
            float2 u = g_i[ib];
            r1 = u.x; t1b = __float_as_int(u.y);
            tmini = fminf(tmini, u.y); tmaxi = fmaxf(tmaxi, u.y);
        }
        __syncthreads();   // sj ready

        // ---- block reduce 4 range values ----
        #pragma unroll
        for (int off = 16; off >= 1; off >>= 1) {
            tminj = fminf(tminj, __shfl_xor_sync(0xffffffffu, tminj, off));
            tmaxj = fmaxf(tmaxj, __shfl_xor_sync(0xffffffffu, tmaxj, off));
            tmini = fminf(tmini, __shfl_xor_sync(0xffffffffu, tmini, off));
            tmaxi = fmaxf(tmaxi, __shfl_xor_sync(0xffffffffu, tmaxi, off));
        }
        if (lane == 0) {
            rmin[0][w] = tminj; rmax[0][w] = tmaxj;
            rmin[1][w] = tmini; rmax[1][w] = tmaxi;
        }
        __syncthreads();
        #pragma unroll
        for (int q = 0; q < TPB2 / 32; q++) {
            tminj = fminf(tminj, rmin[0][q]); tmaxj = fmaxf(tmaxj, rmax[0][q]);
            tmini = fminf(tmini, rmin[1][q]); tmaxi = fmaxf(tmaxi, rmax[1][q]);
        }

        // ---- classify ----
        if (!(tmaxj <= tmini)) {             // not skip
            if (tminj > tmaxi) {
                // FREE: predicate always (strictly) true; count closed-form
                free_blk = true;
                ni_blk = min(ni - i0, ICH);
                nj_blk = min(n - j0, JCH);
                float s0 = 0.f, s1 = 0.f;
                #pragma unroll 8
                for (int k = 0; k < JCH; k++) {
                    float rj = sjr[k];
                    s0 += fmaxf(r0 - rj, 0.0f);
                    s1 += fmaxf(r1 - rj, 0.0f);
                }
                s_acc = s0 + s1;
            } else {
                // MIXED: exact per-pair strict predicate (handles ties/self-pairs)
                float s0 = 0.f, s1 = 0.f;
                int   c0 = 0,   c1 = 0;
                #pragma unroll 8
                for (int k = 0; k < JCH; k++) {
                    float rj  = sjr[k];
                    int   tjb = sjt[k];
                    float h0 = fmaxf(r0 - rj, 0.0f);
                    float h1 = fmaxf(r1 - rj, 0.0f);
                    bool  p0 = tjb > t0b;
                    bool  p1 = tjb > t1b;
                    s0 += p0 ? h0 : 0.0f;
                    s1 += p1 ? h1 : 0.0f;
                    c0 += (int)p0;
                    c1 += (int)p1;
                }
                s_acc = s0 + s1;
                c_acc = c0 + c1;
            }
        }
    }

    // ---- block reduction of s / c, then global accumulation ----
    #pragma unroll
    for (int off = 16; off >= 1; off >>= 1) {
        s_acc += __shfl_down_sync(0xffffffffu, s_acc, off);
        c_acc += __shfl_down_sync(0xffffffffu, c_acc, off);
    }
    if (lane == 0) { swsum[w] = s_acc; swcnt[w] = c_acc; }
    __syncthreads();
    if (tid == 0) {
        float s = 0.f; int c = 0;
        #pragma unroll
        for (int q = 0; q < TPB2 / 32; q++) { s += swsum[q]; c += swcnt[q]; }
        unsigned long long cll = (unsigned long long)c;
        if (free_blk) cll += (unsigned long long)ni_blk * (unsigned long long)nj_blk;
        if (s != 0.0f)  atomicAdd(&g_total, (double)s);
        if (cll != 0ull) atomicAdd(&g_cnt, cll);
        __threadfence();
        unsigned int prev = atomicAdd(&g_done, 1u);
        if (prev == nblocks - 1) {
            __threadfence();
            double tt = *(volatile double*)&g_total;
            unsigned long long cc = *(volatile unsigned long long*)&g_cnt;
            out[0] = (cc == 0ull) ? 0.0f : (float)(tt / (double)cc);
            g_total = 0.0;             // reset: replay-idempotent
            g_cnt   = 0ull;
            g_done  = 0u;
        }
    }
}

extern "C" void kernel_launch(void* const* d_in, const int* in_sizes, int n_in,
                              void* d_out, int out_size) {
    const float* risk  = (const float*)d_in[1];
    const float* time_ = (const float*)d_in[2];
    const int*   event = (const int*)d_in[3];
    const int n = in_sizes[1];

    k_bucket<<<1, TPB1>>>(risk, time_, event, n);

    dim3 g2((n + ICH - 1) / ICH, (n + JCH - 1) / JCH);
    unsigned int nblocks = g2.x * g2.y;
    k_pairs<<<g2, TPB2>>>((float*)d_out, n, nblocks);
}